// round 9
// baseline (speedup 1.0000x reference)
#include <cuda_runtime.h>

// PBKDF2-toy, serial single-warp register kernel. R9: exact pipe balance.
// Model (validated by R5/R8 pair): floor = max(2*alu, 2*fma, total) cyc/iter;
// LOP3 alu-only, adds go IMAD->fma. R5 was 160a/144f, R8 144a/160f -- both
// floor 320, both measured ~349 (neutral, as observed). This round forces
// the 152/152 optimum: all flexible adds pinned to fma via mad.lo with an
// opaque ONE register; F accumulated as 8 packed pairs (IMAD+LOP3) + 16
// singles (LOP3), interleaved into mix round 4. alu=152, fma=152, total=304.
// Harness dtype shims: float32 out, dtype-sniffed in (proven R3).

__device__ __forceinline__ unsigned load_byte(const void* p, int i) {
    int v = ((const int*)p)[i];
    if ((unsigned)v <= 255u) return (unsigned)v;   // int32 input
    return (unsigned)(int)__int_as_float(v);       // float32 input
}

// a + b forced onto the fma pipe: IMAD(a, ONE, b) with runtime ONE=1
// (opaque to ptxas, cannot be strength-reduced to IADD3/alu).
__device__ __forceinline__ unsigned addf(unsigned a, unsigned one, unsigned b) {
    unsigned t;
    asm("mad.lo.u32 %0, %1, %2, %3;" : "=r"(t) : "r"(a), "r"(one), "r"(b));
    return t;
}

// hi*65536 + lo as a single IMAD (fma pipe).
__device__ __forceinline__ unsigned pack16(unsigned hi, unsigned lo) {
    unsigned t;
    asm("mad.lo.u32 %0, %1, 65536, %2;" : "=r"(t) : "r"(hi), "r"(lo));
    return t;
}

__global__ void __launch_bounds__(32, 1)
Model_62955630625117_kernel(const void* __restrict__ pw_in,
                            const void* __restrict__ salt_in,
                            float* __restrict__ out) {
    // All lanes uniform & convergent; lane 0 writes at the end.
    unsigned c[16];     // (pw[j]*31) & 255, loop-invariant
    unsigned r[32];     // hash state U (mix LOP3 keeps bytes 8-bit)
    unsigned Fp[8];     // packed: lo16 = F[j], hi16 = F[j+8]   (j = 0..7)
    unsigned Fh[16];    // singles: F[16..31]

    // Opaque 1 (bytes are <=255 so v>>8 == 0; ptxas can't prove it).
    unsigned ONE = (load_byte(pw_in, 0) >> 8) | 1u;

    #pragma unroll
    for (int j = 0; j < 16; j++) {
        unsigned p = load_byte(pw_in, j);
        c[j] = (p * 31u) & 255u;
        r[j] = p;
    }
    #pragma unroll
    for (int j = 0; j < 16; j++) r[16 + j] = load_byte(salt_in, j);

    // First hmac message = salt(16) ++ block_num{0,0,0,1}
    r[0] = c[0];
    r[1] = c[1];
    r[2] = c[2];
    r[3] = (c[3] + 1u) & 255u;

    // U0 mix
    #pragma unroll
    for (int rd = 0; rd < 4; rd++) {
        #pragma unroll
        for (int i = 0; i < 32; i++)
            r[i] = (r[i] ^ addf(r[(i + 17) & 31], ONE, r[(i + 11) & 31])) & 255u;
    }
    #pragma unroll
    for (int j = 0; j < 8; j++) Fp[j] = pack16(r[j + 8], r[j]);
    #pragma unroll
    for (int k = 0; k < 16; k++) Fh[k] = r[16 + k];

    // 999 chained iterations: U = hmac(pw, U); F ^= U.
    // Absorb collapse: r[j] = c[j] + r[16+j] (9-bit OK, mix LOP3 re-masks),
    // r[16+j] = old r[j] (order-2 swap; even unroll -> pure renaming).
    #pragma unroll 4
    for (int it = 1; it < 1000; it++) {
        #pragma unroll
        for (int j = 0; j < 16; j++) {
            unsigned t = r[j];
            r[j] = addf(c[j], ONE, r[16 + j]);     // IMAD (fma)
            r[16 + j] = t;
        }
        #pragma unroll
        for (int rd = 0; rd < 3; rd++) {
            #pragma unroll
            for (int i = 0; i < 32; i++)
                r[i] = (r[i] ^ addf(r[(i + 17) & 31], ONE, r[(i + 11) & 31])) & 255u;
        }
        // Round 4 with F accumulation interleaved at operand-ready points:
        // steps 0..7 plain
        #pragma unroll
        for (int i = 0; i < 8; i++)
            r[i] = (r[i] ^ addf(r[(i + 17) & 31], ONE, r[(i + 11) & 31])) & 255u;
        // steps 8..15: r[j] (j=i-8) and r[i] both final -> packed pair xor
        #pragma unroll
        for (int i = 8; i < 16; i++) {
            r[i] = (r[i] ^ addf(r[(i + 17) & 31], ONE, r[(i + 11) & 31])) & 255u;
            Fp[i - 8] ^= pack16(r[i], r[i - 8]);   // IMAD (fma) + LOP3 (alu)
        }
        // steps 16..31: singles
        #pragma unroll
        for (int i = 16; i < 32; i++) {
            r[i] = (r[i] ^ addf(r[(i + 17) & 31], ONE, r[(i + 11) & 31])) & 255u;
            Fh[i - 16] ^= r[i];                    // LOP3 (alu)
        }
    }

    if (threadIdx.x == 0) {
        #pragma unroll
        for (int j = 0; j < 8; j++) {
            out[j]     = (float)(Fp[j] & 0xFFFFu);
            out[j + 8] = (float)(Fp[j] >> 16);
        }
        #pragma unroll
        for (int k = 0; k < 16; k++) out[16 + k] = (float)Fh[k];
    }
}

extern "C" void kernel_launch(void* const* d_in, const int* in_sizes, int n_in,
                              void* d_out, int out_size) {
    const void* password = d_in[0];
    const void* salt     = (n_in >= 2) ? d_in[1] : (const void*)((const int*)d_in[0] + 16);
    float* out           = (float*)d_out;
    Model_62955630625117_kernel<<<1, 32>>>(password, salt, out);
}

// round 10
// speedup vs baseline: 1.4826x; 1.4826x over previous
#include <cuda_runtime.h>

// PBKDF2-toy, serial single-warp register kernel. R10: R8 config (best:
// 184.4us, issue 85.7%) with unroll 4 -> 2. Model correction from R9: with
// one warp the bound is total issue slots (~305/iter) + ~58 stall; pipe
// split is irrelevant (R5/R8 equal, forced-balance R9 much worse via asm
// scheduling damage). Unroll-4 body (~19.5KB) is 3x the 6KB L0 I$; unroll 2
// (~9.8KB) halves fetch pressure for +~2 cyc/iter loop overhead. F is
// accumulated as 16 packed halfword pairs (pack16 IMAD + 1 LOP3 each),
// fused into mix round-4 steps 16..31 (proven harmless-to-better in R8).
// Harness dtype shims: float32 out, dtype-sniffed in (proven R3).

__device__ __forceinline__ unsigned load_byte(const void* p, int i) {
    int v = ((const int*)p)[i];
    if ((unsigned)v <= 255u) return (unsigned)v;   // int32 input
    return (unsigned)(int)__int_as_float(v);       // float32 input
}

// hi*65536 + lo as a single IMAD (fma pipe); benign to scheduling (R8).
__device__ __forceinline__ unsigned pack16(unsigned hi, unsigned lo) {
    unsigned t;
    asm("mad.lo.u32 %0, %1, 65536, %2;" : "=r"(t) : "r"(hi), "r"(lo));
    return t;
}

__global__ void __launch_bounds__(32, 1)
Model_62955630625117_kernel(const void* __restrict__ pw_in,
                            const void* __restrict__ salt_in,
                            float* __restrict__ out) {
    // All lanes uniform & convergent; lane 0 writes at the end.
    unsigned c[16];    // (pw[j]*31) & 255, loop-invariant
    unsigned r[32];    // hash state U (mix LOP3 keeps bytes 8-bit)
    unsigned Fp[16];   // packed xor accumulator: lo16 = F[i], hi16 = F[i+16]

    #pragma unroll
    for (int j = 0; j < 16; j++) {
        unsigned p = load_byte(pw_in, j);
        c[j] = (p * 31u) & 255u;
        r[j] = p;
    }
    #pragma unroll
    for (int j = 0; j < 16; j++) r[16 + j] = load_byte(salt_in, j);

    // First hmac message = salt(16) ++ block_num{0,0,0,1}
    r[0] = c[0];
    r[1] = c[1];
    r[2] = c[2];
    r[3] = (c[3] + 1u) & 255u;

    // U0 mix
    #pragma unroll
    for (int rd = 0; rd < 4; rd++) {
        #pragma unroll
        for (int i = 0; i < 32; i++)
            r[i] = (r[i] ^ (r[(i + 17) & 31] + r[(i + 11) & 31])) & 255u;
    }
    #pragma unroll
    for (int i = 0; i < 16; i++)
        Fp[i] = pack16(r[i + 16], r[i]);           // F init = U0 (packed)

    // 999 chained iterations: U = hmac(pw, U); Fp ^= packed(U).
    // Absorb collapse: r[j] = c[j] + r[16+j] (9-bit OK, mix LOP3 re-masks),
    // r[16+j] = old r[j] (order-2 swap; even unroll -> pure renaming).
    #pragma unroll 2
    for (int it = 1; it < 1000; it++) {
        #pragma unroll
        for (int j = 0; j < 16; j++) {
            unsigned t = r[j];
            r[j] = c[j] + r[16 + j];
            r[16 + j] = t;
        }
        #pragma unroll
        for (int rd = 0; rd < 3; rd++) {
            #pragma unroll
            for (int i = 0; i < 32; i++)
                r[i] = (r[i] ^ (r[(i + 17) & 31] + r[(i + 11) & 31])) & 255u;
        }
        // round 4: steps 0..15 plain; steps 16..31 fused with packed F-xor
        #pragma unroll
        for (int i = 0; i < 16; i++)
            r[i] = (r[i] ^ (r[(i + 17) & 31] + r[(i + 11) & 31])) & 255u;
        #pragma unroll
        for (int i = 16; i < 32; i++) {
            r[i] = (r[i] ^ (r[(i + 17) & 31] + r[(i + 11) & 31])) & 255u;
            Fp[i - 16] ^= pack16(r[i], r[i - 16]);  // IMAD (fma) + LOP3 (alu)
        }
    }

    if (threadIdx.x == 0) {
        #pragma unroll
        for (int i = 0; i < 16; i++) {
            out[i]      = (float)(Fp[i] & 0xFFFFu);
            out[i + 16] = (float)(Fp[i] >> 16);
        }
    }
}

extern "C" void kernel_launch(void* const* d_in, const int* in_sizes, int n_in,
                              void* d_out, int out_size) {
    const void* password = d_in[0];
    const void* salt     = (n_in >= 2) ? d_in[1] : (const void*)((const int*)d_in[0] + 16);
    float* out           = (float*)d_out;
    Model_62955630625117_kernel<<<1, 32>>>(password, salt, out);
}